// round 4
// baseline (speedup 1.0000x reference)
#include <cuda_runtime.h>
#include <cuda_bf16.h>
#include <cstdint>

#define CB   4
#define CN   2048
#define CH   8
#define CDH  64
#define CDIM 512
#define ATT_SCALE 0.125f
#define SSTR 72            // smem row stride in bf16 (64 data + 8 pad)

typedef __nv_bfloat16 bf16;

// ---------------- scratch (__device__ globals; no allocation allowed) -------
__device__ bf16 g_xhi[CB * CN * CDIM];
__device__ bf16 g_xlo[CB * CN * CDIM];
__device__ bf16 g_qh[CB * CN * CDIM];
__device__ bf16 g_ql[CB * CN * CDIM];
__device__ bf16 g_kh[CB * CN * CDIM];
__device__ bf16 g_kl[CB * CN * CDIM];
__device__ bf16 g_vh[CB * CN * CDIM];
__device__ bf16 g_vl[CB * CN * CDIM];
__device__ bf16 g_ohi[CB * CN * CDIM];
__device__ bf16 g_olo[CB * CN * CDIM];
__device__ bf16 g_wh[4][CDIM * CDIM];
__device__ bf16 g_wl[4][CDIM * CDIM];

// ---------------- helpers ----------------------------------------------------
__device__ __forceinline__ void mma16816(float* c, const uint32_t* a, uint32_t b0, uint32_t b1) {
    asm volatile(
        "mma.sync.aligned.m16n8k16.row.col.f32.bf16.bf16.f32 "
        "{%0,%1,%2,%3}, {%4,%5,%6,%7}, {%8,%9}, {%0,%1,%2,%3};\n"
        : "+f"(c[0]), "+f"(c[1]), "+f"(c[2]), "+f"(c[3])
        : "r"(a[0]), "r"(a[1]), "r"(a[2]), "r"(a[3]), "r"(b0), "r"(b1));
}
__device__ __forceinline__ uint32_t packbf(bf16 x, bf16 y) {
    __nv_bfloat162 t = __halves2bfloat162(x, y);
    return *reinterpret_cast<uint32_t*>(&t);
}
__device__ __forceinline__ uint32_t smem_u32(const void* p) {
    uint32_t a;
    asm("{ .reg .u64 t; cvta.to.shared.u64 t, %1; cvt.u32.u64 %0, t; }" : "=r"(a) : "l"(p));
    return a;
}
__device__ __forceinline__ void cp_async16(uint32_t saddr, const void* g) {
    asm volatile("cp.async.cg.shared.global [%0], [%1], 16;" :: "r"(saddr), "l"(g));
}
__device__ __forceinline__ void cp_commit() { asm volatile("cp.async.commit_group;"); }
template<int N> __device__ __forceinline__ void cp_wait() {
    asm volatile("cp.async.wait_group %0;" :: "n"(N));
}
// split helper: v -> (hi, lo)
__device__ __forceinline__ void split2(float v, bf16& h, bf16& l) {
    h = __float2bfloat16(v);
    l = __float2bfloat16(v - __bfloat162float(h));
}

// ---------------- fp32 -> bf16 hi/lo split -----------------------------------
__global__ void split_kernel(const float* __restrict__ src,
                             bf16* __restrict__ hi, bf16* __restrict__ lo, int n)
{
    int i = (blockIdx.x * blockDim.x + threadIdx.x) * 4;
    if (i >= n) return;
    float4 v = *(const float4*)(src + i);
    bf16 h0, h1, h2, h3, l0, l1, l2, l3;
    split2(v.x, h0, l0); split2(v.y, h1, l1);
    split2(v.z, h2, l2); split2(v.w, h3, l3);
    *(uint32_t*)(hi + i)     = packbf(h0, h1);
    *(uint32_t*)(hi + i + 2) = packbf(h2, h3);
    *(uint32_t*)(lo + i)     = packbf(l0, l1);
    *(uint32_t*)(lo + i + 2) = packbf(l2, l3);
}

// ---------------- GEMM mainloop (shared via macro) ---------------------------
// acc[2][8][4]; 128x128 tile; K=512 in 8 chunks of 64; 2-stage cp.async pipeline.
#define TEN_B   (128 * SSTR * 2)
#define STAGE_B (4 * TEN_B)

#define GEMM_LOAD_CHUNK(st, kc)                                                   \
    {                                                                             \
        _Pragma("unroll")                                                         \
        for (int i = 0; i < 4; i++) {                                             \
            int idx = tid + 256 * i;                                              \
            int r = idx >> 3, u = idx & 7;                                        \
            uint32_t so = sbase + (uint32_t)((st) * STAGE_B + (r * SSTR + 8 * u) * 2); \
            cp_async16(so + 0 * TEN_B, Ah_g + (size_t)(rowBase + r) * CDIM + (kc) + 8 * u); \
            cp_async16(so + 1 * TEN_B, Al_g + (size_t)(rowBase + r) * CDIM + (kc) + 8 * u); \
            cp_async16(so + 2 * TEN_B, Bh_g + (size_t)(colBase + r) * CDIM + (kc) + 8 * u); \
            cp_async16(so + 3 * TEN_B, Bl_g + (size_t)(colBase + r) * CDIM + (kc) + 8 * u); \
        }                                                                         \
        cp_commit();                                                              \
    }

#define GEMM_COMPUTE_CHUNK(st)                                                    \
    {                                                                             \
        const bf16* Ah = gs + (st) * 4 * 128 * SSTR;                              \
        const bf16* Al = Ah + 128 * SSTR;                                         \
        const bf16* Bh = Al + 128 * SSTR;                                         \
        const bf16* Bl = Bh + 128 * SSTR;                                         \
        _Pragma("unroll")                                                         \
        for (int ka = 0; ka < 4; ka++) {                                          \
            const int ko = 16 * ka + 2 * tig;                                     \
            uint32_t a_h[2][4], a_l[2][4];                                        \
            _Pragma("unroll")                                                     \
            for (int m = 0; m < 2; m++) {                                         \
                int rb = 32 * wM + 16 * m;                                        \
                a_h[m][0] = *(const uint32_t*)&Ah[(rb + g)     * SSTR + ko];      \
                a_h[m][1] = *(const uint32_t*)&Ah[(rb + g + 8) * SSTR + ko];      \
                a_h[m][2] = *(const uint32_t*)&Ah[(rb + g)     * SSTR + ko + 8];  \
                a_h[m][3] = *(const uint32_t*)&Ah[(rb + g + 8) * SSTR + ko + 8];  \
                a_l[m][0] = *(const uint32_t*)&Al[(rb + g)     * SSTR + ko];      \
                a_l[m][1] = *(const uint32_t*)&Al[(rb + g + 8) * SSTR + ko];      \
                a_l[m][2] = *(const uint32_t*)&Al[(rb + g)     * SSTR + ko + 8];  \
                a_l[m][3] = *(const uint32_t*)&Al[(rb + g + 8) * SSTR + ko + 8];  \
            }                                                                     \
            _Pragma("unroll")                                                     \
            for (int j = 0; j < 8; j++) {                                         \
                int cr = 64 * wN + 8 * j + g;                                     \
                uint32_t b0h = *(const uint32_t*)&Bh[cr * SSTR + ko];             \
                uint32_t b1h = *(const uint32_t*)&Bh[cr * SSTR + ko + 8];         \
                uint32_t b0l = *(const uint32_t*)&Bl[cr * SSTR + ko];             \
                uint32_t b1l = *(const uint32_t*)&Bl[cr * SSTR + ko + 8];         \
                _Pragma("unroll")                                                 \
                for (int m = 0; m < 2; m++) {                                     \
                    mma16816(acc[m][j], a_h[m], b0h, b1h);                        \
                    mma16816(acc[m][j], a_h[m], b0l, b1l);                        \
                    mma16816(acc[m][j], a_l[m], b0h, b1h);                        \
                }                                                                 \
            }                                                                     \
        }                                                                         \
    }

#define GEMM_PREAMBLE()                                                           \
    const int tid  = threadIdx.x;                                                 \
    const int w    = tid >> 5;                                                    \
    const int lane = tid & 31;                                                    \
    const int g    = lane >> 2;                                                   \
    const int tig  = lane & 3;                                                    \
    const int wM   = w >> 1;                                                      \
    const int wN   = w & 1;                                                       \
    float acc[2][8][4];                                                           \
    _Pragma("unroll")                                                             \
    for (int m = 0; m < 2; m++)                                                   \
        _Pragma("unroll")                                                         \
        for (int j = 0; j < 8; j++)                                               \
            _Pragma("unroll")                                                     \
            for (int t = 0; t < 4; t++) acc[m][j][t] = 0.f;

#define GEMM_MAINLOOP()                                                           \
    GEMM_LOAD_CHUNK(0, 0)                                                         \
    _Pragma("unroll 1")                                                           \
    for (int ch = 0; ch < 8; ch++) {                                              \
        if (ch + 1 < 8) GEMM_LOAD_CHUNK((ch + 1) & 1, 64 * (ch + 1))              \
        if (ch + 1 < 8) cp_wait<1>(); else cp_wait<0>();                          \
        __syncthreads();                                                          \
        GEMM_COMPUTE_CHUNK(ch & 1)                                                \
        __syncthreads();                                                          \
    }

// ---------------- fused QKV projection (bf16 split output) -------------------
__global__ __launch_bounds__(256, 1) void qkv_gemm_kernel(
    const bf16* __restrict__ Ah_g, const bf16* __restrict__ Al_g,
    const bf16* __restrict__ w0h, const bf16* __restrict__ w0l,
    const bf16* __restrict__ w1h, const bf16* __restrict__ w1l,
    const bf16* __restrict__ w2h, const bf16* __restrict__ w2l,
    bf16* __restrict__ q_h, bf16* __restrict__ q_l,
    bf16* __restrict__ k_h, bf16* __restrict__ k_l,
    bf16* __restrict__ v_h, bf16* __restrict__ v_l)
{
    extern __shared__ bf16 gs[];
    const uint32_t sbase = smem_u32(gs);
    const int wsel    = blockIdx.x >> 2;
    const int colBase = (blockIdx.x & 3) * 128;
    const int rowBase = blockIdx.y * 128;
    const bf16* Bh_g = (wsel == 0) ? w0h : (wsel == 1) ? w1h : w2h;
    const bf16* Bl_g = (wsel == 0) ? w0l : (wsel == 1) ? w1l : w2l;
    bf16* outH = (wsel == 0) ? q_h : (wsel == 1) ? k_h : v_h;
    bf16* outL = (wsel == 0) ? q_l : (wsel == 1) ? k_l : v_l;
    const float scale = (wsel == 0) ? ATT_SCALE : 1.0f;

    GEMM_PREAMBLE()
    GEMM_MAINLOOP()

#pragma unroll
    for (int m = 0; m < 2; m++)
#pragma unroll
        for (int j = 0; j < 8; j++) {
            int row = rowBase + 32 * wM + 16 * m + g;
            int col = colBase + 64 * wN + 8 * j + 2 * tig;
            bf16 h0, h1, h2, h3, l0, l1, l2, l3;
            split2(acc[m][j][0] * scale, h0, l0);
            split2(acc[m][j][1] * scale, h1, l1);
            split2(acc[m][j][2] * scale, h2, l2);
            split2(acc[m][j][3] * scale, h3, l3);
            *(uint32_t*)&outH[(size_t)row * CDIM + col]       = packbf(h0, h1);
            *(uint32_t*)&outL[(size_t)row * CDIM + col]       = packbf(l0, l1);
            *(uint32_t*)&outH[(size_t)(row + 8) * CDIM + col] = packbf(h2, h3);
            *(uint32_t*)&outL[(size_t)(row + 8) * CDIM + col] = packbf(l2, l3);
        }
}

// ---------------- output projection (fp32 out) -------------------------------
__global__ __launch_bounds__(256, 1) void out_gemm_kernel(
    const bf16* __restrict__ Ah_g, const bf16* __restrict__ Al_g,
    const bf16* __restrict__ Bh_g, const bf16* __restrict__ Bl_g,
    float* __restrict__ C)
{
    extern __shared__ bf16 gs[];
    const uint32_t sbase = smem_u32(gs);
    const int colBase = blockIdx.x * 128;
    const int rowBase = blockIdx.y * 128;

    GEMM_PREAMBLE()
    GEMM_MAINLOOP()

#pragma unroll
    for (int m = 0; m < 2; m++)
#pragma unroll
        for (int j = 0; j < 8; j++) {
            int row = rowBase + 32 * wM + 16 * m + g;
            int col = colBase + 64 * wN + 8 * j + 2 * tig;
            *(float2*)&C[(size_t)row * CDIM + col]       = make_float2(acc[m][j][0], acc[m][j][1]);
            *(float2*)&C[(size_t)(row + 8) * CDIM + col] = make_float2(acc[m][j][2], acc[m][j][3]);
        }
}

// ---------------- flash attention (pre-split bf16 in/out) --------------------
// 128 queries / block, 8 warps x 16 rows, key tiles of 64, Dh = 64.
__global__ __launch_bounds__(256, 1) void attn_mma_kernel(
    const bf16* __restrict__ qh_g, const bf16* __restrict__ ql_g,
    const bf16* __restrict__ kh_g, const bf16* __restrict__ kl_g,
    const bf16* __restrict__ vh_g, const bf16* __restrict__ vl_g,
    const int* __restrict__ mask,
    bf16* __restrict__ OH, bf16* __restrict__ OL)
{
    extern __shared__ bf16 sm[];
    bf16* Kh = sm;                    // [key][dh]
    bf16* Kl = Kh + 64 * SSTR;
    bf16* Vh = Kl + 64 * SSTR;        // transposed [dh][key]
    bf16* Vl = Vh + 64 * SSTR;
    bf16* Qs = Vl + 64 * SSTR;        // staging, reused for Qh then Ql
    int*  Ms = (int*)(Qs + 128 * SSTR);

    const int tid  = threadIdx.x;
    const int w    = tid >> 5;
    const int lane = tid & 31;
    const int g    = lane >> 2;
    const int tig  = lane & 3;
    const int q0   = blockIdx.x * 128;
    const int h    = blockIdx.y & 7;
    const int b    = blockIdx.y >> 3;
    const int cb   = h * CDH;

    // ---- preload Q fragments (hi then lo via shared staging) ----
    uint32_t qfh[4][4], qfl[4][4];
#pragma unroll
    for (int pass = 0; pass < 2; pass++) {
        const bf16* src = pass ? ql_g : qh_g;
#pragma unroll
        for (int i = 0; i < 4; i++) {
            int idx = tid + 256 * i;         // 0..1023 uint4
            int r = idx >> 3, u = idx & 7;
            *(uint4*)&Qs[r * SSTR + 8 * u] =
                *((const uint4*)(src + (size_t)(b * CN + q0 + r) * CDIM + cb) + u);
        }
        __syncthreads();
        uint32_t (*dst)[4] = pass ? qfl : qfh;
#pragma unroll
        for (int ka = 0; ka < 4; ka++) {
            int rb = 16 * w;
            int ko = 16 * ka + 2 * tig;
            dst[ka][0] = *(const uint32_t*)&Qs[(rb + g)     * SSTR + ko];
            dst[ka][1] = *(const uint32_t*)&Qs[(rb + g + 8) * SSTR + ko];
            dst[ka][2] = *(const uint32_t*)&Qs[(rb + g)     * SSTR + ko + 8];
            dst[ka][3] = *(const uint32_t*)&Qs[(rb + g + 8) * SSTR + ko + 8];
        }
        __syncthreads();
    }

    float o[8][4];
#pragma unroll
    for (int n = 0; n < 8; n++)
#pragma unroll
        for (int t = 0; t < 4; t++) o[n][t] = 0.f;
    float m0 = -1e30f, m1 = -1e30f, l0 = 0.f, l1 = 0.f;

    for (int kb = 0; kb < CN; kb += 64) {
        __syncthreads();

        // K tile (straight bf16 copies, [key][dh])
#pragma unroll
        for (int i = 0; i < 2; i++) {
            int idx = tid + 256 * i;         // 0..511 uint4
            int r = idx >> 3, u = idx & 7;
            *(uint4*)&Kh[r * SSTR + 8 * u] =
                *((const uint4*)(kh_g + (size_t)(b * CN + kb + r) * CDIM + cb) + u);
            *(uint4*)&Kl[r * SSTR + 8 * u] =
                *((const uint4*)(kl_g + (size_t)(b * CN + kb + r) * CDIM + cb) + u);
        }
        // V tile transposed: Vh[dh][key] (scalar bf16 gathers, packed stores)
        {
            int d = tid & 63;
            int kg0 = tid >> 6;              // 0..3
#pragma unroll
            for (int kgi = 0; kgi < 2; kgi++) {
                int kg = kg0 + 4 * kgi;      // 0..7
                bf16 hv[8], lv[8];
#pragma unroll
                for (int i = 0; i < 8; i++) {
                    size_t gi = (size_t)(b * CN + kb + kg * 8 + i) * CDIM + cb + d;
                    hv[i] = vh_g[gi];
                    lv[i] = vl_g[gi];
                }
#pragma unroll
                for (int p = 0; p < 4; p++) {
                    *(uint32_t*)&Vh[d * SSTR + kg * 8 + 2 * p] = packbf(hv[2 * p], hv[2 * p + 1]);
                    *(uint32_t*)&Vl[d * SSTR + kg * 8 + 2 * p] = packbf(lv[2 * p], lv[2 * p + 1]);
                }
            }
        }
        if (tid < 64) Ms[tid] = mask[b * CN + kb + tid];
        __syncthreads();

        // ---- S = Q K^T (3-pass split) ----
        float s[8][4];
#pragma unroll
        for (int j = 0; j < 8; j++)
#pragma unroll
            for (int t = 0; t < 4; t++) s[j][t] = 0.f;
#pragma unroll
        for (int ka = 0; ka < 4; ka++) {
            const int ko = 16 * ka + 2 * tig;
#pragma unroll
            for (int j = 0; j < 8; j++) {
                int kr = 8 * j + g;
                uint32_t b0h = *(const uint32_t*)&Kh[kr * SSTR + ko];
                uint32_t b1h = *(const uint32_t*)&Kh[kr * SSTR + ko + 8];
                uint32_t b0l = *(const uint32_t*)&Kl[kr * SSTR + ko];
                uint32_t b1l = *(const uint32_t*)&Kl[kr * SSTR + ko + 8];
                mma16816(s[j], qfh[ka], b0h, b1h);
                mma16816(s[j], qfh[ka], b0l, b1l);
                mma16816(s[j], qfl[ka], b0h, b1h);
            }
        }

        // ---- constant masked-fill (1e-9, per reference) ----
#pragma unroll
        for (int j = 0; j < 8; j++) {
            int k0 = 8 * j + 2 * tig;
            if (Ms[k0]     == 0) { s[j][0] = 1e-9f; s[j][2] = 1e-9f; }
            if (Ms[k0 + 1] == 0) { s[j][1] = 1e-9f; s[j][3] = 1e-9f; }
        }

        // ---- online softmax ----
        float rm0 = -1e30f, rm1 = -1e30f;
#pragma unroll
        for (int j = 0; j < 8; j++) {
            rm0 = fmaxf(rm0, fmaxf(s[j][0], s[j][1]));
            rm1 = fmaxf(rm1, fmaxf(s[j][2], s[j][3]));
        }
        rm0 = fmaxf(rm0, __shfl_xor_sync(0xffffffffu, rm0, 1));
        rm0 = fmaxf(rm0, __shfl_xor_sync(0xffffffffu, rm0, 2));
        rm1 = fmaxf(rm1, __shfl_xor_sync(0xffffffffu, rm1, 1));
        rm1 = fmaxf(rm1, __shfl_xor_sync(0xffffffffu, rm1, 2));
        float mn0 = fmaxf(m0, rm0), mn1 = fmaxf(m1, rm1);
        float al0 = __expf(m0 - mn0), al1 = __expf(m1 - mn1);
        m0 = mn0; m1 = mn1;
        float rs0 = 0.f, rs1 = 0.f;
#pragma unroll
        for (int j = 0; j < 8; j++) {
            s[j][0] = __expf(s[j][0] - m0); rs0 += s[j][0];
            s[j][1] = __expf(s[j][1] - m0); rs0 += s[j][1];
            s[j][2] = __expf(s[j][2] - m1); rs1 += s[j][2];
            s[j][3] = __expf(s[j][3] - m1); rs1 += s[j][3];
        }
        rs0 += __shfl_xor_sync(0xffffffffu, rs0, 1);
        rs0 += __shfl_xor_sync(0xffffffffu, rs0, 2);
        rs1 += __shfl_xor_sync(0xffffffffu, rs1, 1);
        rs1 += __shfl_xor_sync(0xffffffffu, rs1, 2);
        l0 = l0 * al0 + rs0;
        l1 = l1 * al1 + rs1;
#pragma unroll
        for (int n = 0; n < 8; n++) {
            o[n][0] *= al0; o[n][1] *= al0; o[n][2] *= al1; o[n][3] *= al1;
        }

        // ---- O += P V (P re-split in regs; 3-pass) ----
#pragma unroll
        for (int ka = 0; ka < 4; ka++) {
            const int j0 = 2 * ka, j1 = 2 * ka + 1;
            uint32_t ph[4], pl[4];
            {
                bf16 h00, h01, h02, h03, h10, h11, h12, h13;
                bf16 e00, e01, e02, e03, e10, e11, e12, e13;
                split2(s[j0][0], h00, e00); split2(s[j0][1], h01, e01);
                split2(s[j0][2], h02, e02); split2(s[j0][3], h03, e03);
                split2(s[j1][0], h10, e10); split2(s[j1][1], h11, e11);
                split2(s[j1][2], h12, e12); split2(s[j1][3], h13, e13);
                ph[0] = packbf(h00, h01); ph[1] = packbf(h02, h03);
                ph[2] = packbf(h10, h11); ph[3] = packbf(h12, h13);
                pl[0] = packbf(e00, e01); pl[1] = packbf(e02, e03);
                pl[2] = packbf(e10, e11); pl[3] = packbf(e12, e13);
            }
            const int ko = 16 * ka + 2 * tig;
#pragma unroll
            for (int n = 0; n < 8; n++) {
                int vr = 8 * n + g;
                uint32_t b0h = *(const uint32_t*)&Vh[vr * SSTR + ko];
                uint32_t b1h = *(const uint32_t*)&Vh[vr * SSTR + ko + 8];
                uint32_t b0l = *(const uint32_t*)&Vl[vr * SSTR + ko];
                uint32_t b1l = *(const uint32_t*)&Vl[vr * SSTR + ko + 8];
                mma16816(o[n], ph, b0h, b1h);
                mma16816(o[n], pl, b0h, b1h);
                mma16816(o[n], ph, b0l, b1l);
            }
        }
    }

    // ---- epilogue: normalize + hi/lo split store ----
    float inv0 = 1.f / l0, inv1 = 1.f / l1;
    int qr = q0 + 16 * w + g;
#pragma unroll
    for (int n = 0; n < 8; n++) {
        int col = cb + 8 * n + 2 * tig;
        float a0 = o[n][0] * inv0, a1 = o[n][1] * inv0;
        float a2 = o[n][2] * inv1, a3 = o[n][3] * inv1;
        bf16 h0, h1, h2, h3, e0, e1, e2, e3;
        split2(a0, h0, e0); split2(a1, h1, e1);
        split2(a2, h2, e2); split2(a3, h3, e3);
        *(uint32_t*)&OH[(size_t)(b * CN + qr) * CDIM + col]     = packbf(h0, h1);
        *(uint32_t*)&OL[(size_t)(b * CN + qr) * CDIM + col]     = packbf(e0, e1);
        *(uint32_t*)&OH[(size_t)(b * CN + qr + 8) * CDIM + col] = packbf(h2, h3);
        *(uint32_t*)&OL[(size_t)(b * CN + qr + 8) * CDIM + col] = packbf(e2, e3);
    }
}

// ---------------------------------------------------------------------------
extern "C" void kernel_launch(void* const* d_in, const int* in_sizes, int n_in,
                              void* d_out, int out_size)
{
    const float* x    = (const float*)d_in[0];
    const int*   mask = (const int*)  d_in[1];
    const float* W[4] = { (const float*)d_in[2], (const float*)d_in[3],
                          (const float*)d_in[4], (const float*)d_in[5] };
    float* out = (float*)d_out;

    bf16 *xh, *xl, *qh, *ql, *kh, *kl, *vh, *vl, *oh, *ol, *wh, *wl;
    cudaGetSymbolAddress((void**)&xh, g_xhi);
    cudaGetSymbolAddress((void**)&xl, g_xlo);
    cudaGetSymbolAddress((void**)&qh, g_qh);
    cudaGetSymbolAddress((void**)&ql, g_ql);
    cudaGetSymbolAddress((void**)&kh, g_kh);
    cudaGetSymbolAddress((void**)&kl, g_kl);
    cudaGetSymbolAddress((void**)&vh, g_vh);
    cudaGetSymbolAddress((void**)&vl, g_vl);
    cudaGetSymbolAddress((void**)&oh, g_ohi);
    cudaGetSymbolAddress((void**)&ol, g_olo);
    cudaGetSymbolAddress((void**)&wh, g_wh);
    cudaGetSymbolAddress((void**)&wl, g_wl);

    const int M  = CB * CN;            // 8192
    const int NX = M * CDIM;
    const int NW = CDIM * CDIM;

    split_kernel<<<NX / 4 / 256, 256>>>(x, xh, xl, NX);
    for (int w = 0; w < 4; w++)
        split_kernel<<<NW / 4 / 256, 256>>>(W[w], wh + (size_t)w * NW, wl + (size_t)w * NW, NW);

    const int gsm = 2 * STAGE_B;                                   // 147456
    const int asmb = (4 * 64 + 128) * SSTR * (int)sizeof(bf16) + 64 * (int)sizeof(int);
    cudaFuncSetAttribute(qkv_gemm_kernel, cudaFuncAttributeMaxDynamicSharedMemorySize, gsm);
    cudaFuncSetAttribute(out_gemm_kernel, cudaFuncAttributeMaxDynamicSharedMemorySize, gsm);
    cudaFuncSetAttribute(attn_mma_kernel, cudaFuncAttributeMaxDynamicSharedMemorySize, asmb);

    qkv_gemm_kernel<<<dim3(12, M / 128), 256, gsm>>>(
        xh, xl,
        wh + 0 * (size_t)NW, wl + 0 * (size_t)NW,
        wh + 1 * (size_t)NW, wl + 1 * (size_t)NW,
        wh + 2 * (size_t)NW, wl + 2 * (size_t)NW,
        qh, ql, kh, kl, vh, vl);

    attn_mma_kernel<<<dim3(CN / 128, CH * CB), 256, asmb>>>(
        qh, ql, kh, kl, vh, vl, mask, oh, ol);

    out_gemm_kernel<<<dim3(CDIM / 128, M / 128), 256, gsm>>>(
        oh, ol, wh + 3 * (size_t)NW, wl + 3 * (size_t)NW, out);
}